// round 7
// baseline (speedup 1.0000x reference)
#include <cuda_runtime.h>
#include <cuda_bf16.h>
#include <cstdint>

#define BB      8
#define NP      4096
#define NS      1024
#define NC      (BB*NS)
#define KNBR    64
#define CIN     64
#define HH      128
#define R2f     0.04f
#define CAP     768
#define NBALL   32
#define NGRID   148
#define NGTASK  1024
#define NBTASK  1024
#define NTTASK  4096
#define BSTR    272            // bf16 tile row stride in bytes (136 bf16, conflict-free)

// ---------------- device scratch ----------------
__device__ float g_feat[BB*NP*HH];
__device__ int   fpsflag[NC];          // idx+1 when ready
__device__ int   ballflag[NC];         // 1 when nbr/ctr ready
__device__ int   d_nbr[NC*KNBR];       // padded to 64 (dup of nbr 0)
__device__ float d_ctr[NC*3];
__device__ int   d_sync[4];            // 0:g_ctr 1:ball_ctr 2:gemm_ctr 3:g_done

// ---------------- helpers ----------------
__device__ __forceinline__ float dist2(float ax,float ay,float az,float bx,float by,float bz){
    float dx = ax-bx, dy = ay-by, dz = az-bz;
    return __fadd_rn(__fadd_rn(__fmul_rn(dx,dx),__fmul_rn(dy,dy)),__fmul_rn(dz,dz));
}
__device__ __forceinline__ unsigned long long packf2(float lo, float hi){
    unsigned long long r; asm("mov.b64 %0, {%1, %2};" : "=l"(r) : "f"(lo), "f"(hi)); return r;
}
__device__ __forceinline__ void unpackf2(unsigned long long v, float& lo, float& hi){
    asm("mov.b64 {%0, %1}, %2;" : "=f"(lo), "=f"(hi) : "l"(v));
}
__device__ __forceinline__ unsigned long long addf2(unsigned long long a, unsigned long long b){
    unsigned long long d; asm("add.rn.f32x2 %0, %1, %2;" : "=l"(d) : "l"(a), "l"(b)); return d;
}
__device__ __forceinline__ unsigned long long mulf2(unsigned long long a, unsigned long long b){
    unsigned long long d; asm("mul.rn.f32x2 %0, %1, %2;" : "=l"(d) : "l"(a), "l"(b)); return d;
}
__device__ __forceinline__ uint32_t smem_u32(const void* p){
    uint32_t a;
    asm("{ .reg .u64 t; cvta.to.shared.u64 t, %1; cvt.u32.u64 %0, t; }" : "=r"(a) : "l"(p));
    return a;
}
__device__ __forceinline__ int ld_acq(const int* p){
    int v; asm volatile("ld.acquire.gpu.s32 %0, [%1];" : "=r"(v) : "l"(p) : "memory"); return v;
}
__device__ __forceinline__ void st_rel(int* p, int v){
    asm volatile("st.release.gpu.s32 [%0], %1;" :: "l"(p), "r"(v) : "memory");
}
__device__ __forceinline__ void ldsm4(uint32_t& r0,uint32_t& r1,uint32_t& r2,uint32_t& r3,uint32_t a){
    asm volatile("ldmatrix.sync.aligned.m8n8.x4.shared.b16 {%0,%1,%2,%3}, [%4];"
        : "=r"(r0),"=r"(r1),"=r"(r2),"=r"(r3) : "r"(a));
}
__device__ __forceinline__ void ldsm4t(uint32_t& r0,uint32_t& r1,uint32_t& r2,uint32_t& r3,uint32_t a){
    asm volatile("ldmatrix.sync.aligned.m8n8.x4.trans.shared.b16 {%0,%1,%2,%3}, [%4];"
        : "=r"(r0),"=r"(r1),"=r"(r2),"=r"(r3) : "r"(a));
}
__device__ __forceinline__ void mma16816(float* d, const uint32_t* a, const uint32_t* b){
    asm volatile("mma.sync.aligned.m16n8k16.row.col.f32.bf16.bf16.f32 "
        "{%0,%1,%2,%3}, {%4,%5,%6,%7}, {%8,%9}, {%0,%1,%2,%3};"
        : "+f"(d[0]),"+f"(d[1]),"+f"(d[2]),"+f"(d[3])
        : "r"(a[0]),"r"(a[1]),"r"(a[2]),"r"(a[3]), "r"(b[0]),"r"(b[1]));
}

// ---------------- smem layout ----------------
#define OA_HI   0                        // A = W2^T bf16 hi: [m 128][BSTR] = 34816
#define OA_LO   34816
#define OB_HI   69632                    // B = h1 bf16 hi: [k 128][BSTR]
#define OB_LO   104448
#define OWB     139264                   // float4[128]: (b1, w1x, w1y, w1z)
#define ODP     141312                   // float4[128]
#define OGJ     143360                   // int[128]
#define OTASK   143872
#define SM_TOT  143888

// ================= roles =================
__device__ void fps_role(char* smem, const float* __restrict__ pos, int b)
{
    float* px = (float*)smem;
    float* py = px + NP;
    float* pz = py + NP;
    unsigned long long* sbuf = (unsigned long long*)(pz + NP); // [2][8]
    int tid = threadIdx.x;

    const float* pb = pos + (size_t)b*NP*3;
    for (int i = tid; i < NP; i += 256) {
        px[i] = pb[i*3+0]; py[i] = pb[i*3+1]; pz[i] = pb[i*3+2];
    }
    if (tid == 0) st_rel(&fpsflag[b*NS], 1);   // sample 0 = point 0
    __syncthreads();

    int ibase = tid << 4;
    unsigned long long rpx[8], rpy[8], rpz[8];
    float md[16];
    #pragma unroll
    for (int j = 0; j < 8; ++j) {
        rpx[j] = packf2(px[ibase+2*j], px[ibase+2*j+1]);
        rpy[j] = packf2(py[ibase+2*j], py[ibase+2*j+1]);
        rpz[j] = packf2(pz[ibase+2*j], pz[ibase+2*j+1]);
    }
    #pragma unroll
    for (int t = 0; t < 16; ++t) md[t] = 1e10f;

    int lane = tid & 31, warp = tid >> 5;
    int last = 0;
    for (int s = 1; s < NS; ++s) {
        float lx = px[last], ly = py[last], lz = pz[last];
        unsigned long long nx = packf2(-lx,-lx), ny = packf2(-ly,-ly), nz = packf2(-lz,-lz);
        #pragma unroll
        for (int j = 0; j < 8; ++j) {
            unsigned long long dx = addf2(rpx[j], nx);
            unsigned long long dy = addf2(rpy[j], ny);
            unsigned long long dz = addf2(rpz[j], nz);
            unsigned long long sD = addf2(addf2(mulf2(dx,dx), mulf2(dy,dy)), mulf2(dz,dz));
            float s0, s1; unpackf2(sD, s0, s1);
            md[2*j]   = fminf(md[2*j],   s0);
            md[2*j+1] = fminf(md[2*j+1], s1);
        }
        float bv = md[0]; int bt = 0;
        #pragma unroll
        for (int t = 1; t < 16; ++t)
            if (md[t] > bv) { bv = md[t]; bt = t; }

        unsigned vbits = __float_as_uint(bv);
        unsigned vm = __reduce_max_sync(0xffffffffu, vbits);
        unsigned msk = __ballot_sync(0xffffffffu, vbits == vm);
        int src = __ffs(msk) - 1;
        int bidx = __shfl_sync(0xffffffffu, ibase + bt, src);

        unsigned long long* slot = sbuf + (s & 1)*8;
        if (lane == 0)
            slot[warp] = ((unsigned long long)vm << 32) | (unsigned)(NP - 1 - bidx);
        __syncthreads();
        unsigned long long w = slot[0];
        #pragma unroll
        for (int k = 1; k < 8; ++k) { unsigned long long v = slot[k]; if (v > w) w = v; }
        last = NP - 1 - (int)(unsigned)(w & 0xffffffffull);
        if (tid == 0) st_rel(&fpsflag[b*NS + s], last + 1);
    }
}

__device__ void ball_role(char* smem, const float* __restrict__ pos,
                          float* __restrict__ out, int mode)
{
    float* px = (float*)smem;
    float* py = px + NP;
    float* pz = py + NP;
    unsigned long long* cball = (unsigned long long*)(pz + NP);
    int* stask = (int*)(smem + OTASK);
    int tid = threadIdx.x, lane = tid & 31, wid = tid >> 5;

    for (;;) {
        __syncthreads();
        if (tid == 0) *stask = atomicAdd(&d_sync[1], 1);
        __syncthreads();
        int c = *stask;
        if (c >= NBTASK) break;
        int cloud = c & 7, lc = c >> 3;

        const float* pb = pos + (size_t)cloud*NP*3;
        for (int i = tid; i < NP; i += 256) {
            px[i] = pb[i*3+0]; py[i] = pb[i*3+1]; pz[i] = pb[i*3+2];
        }
        __syncthreads();

        int cg = cloud*NS + lc*8 + wid;

        int v = 0;
        if (lane == 0) while ((v = ld_acq(&fpsflag[cg])) == 0) {}
        v = __shfl_sync(0xffffffffu, v, 0);
        int ci = v - 1;

        float cx = px[ci], cy = py[ci], cz = pz[ci];
        if (lane == 0) {
            d_ctr[cg*3+0] = cx; d_ctr[cg*3+1] = cy; d_ctr[cg*3+2] = cz;
            if (mode & 1) {
                out[NC*HH + cg*3+0] = cx;
                out[NC*HH + cg*3+1] = cy;
                out[NC*HH + cg*3+2] = cz;
            }
            if (mode & 2) out[NC*HH + NC*3 + cg] = (float)cloud;
        }

        unsigned long long* cb = cball + (size_t)wid * CAP;
        unsigned cnt = 0;
        for (int j = lane; j < NP; j += 32) {
            float d2 = dist2(px[j],py[j],pz[j],cx,cy,cz);
            bool in = (d2 <= R2f);
            unsigned m = __ballot_sync(0xffffffffu, in);
            if (in) {
                unsigned o = cnt + __popc(m & ((1u << lane) - 1u));
                if (o < CAP)
                    cb[o] = ((unsigned long long)__float_as_uint(d2) << 32) | (unsigned)j;
            }
            cnt += __popc(m);
        }
        if (cnt > CAP) cnt = CAP;

        int base = cg * KNBR;
        if (cnt <= KNBR) {
            int firstIdx = cloud*NP + (int)(unsigned)(cb[0] & 0xffffffffull);
            for (int t = lane; t < KNBR; t += 32)
                d_nbr[base + t] = (t < (int)cnt)
                    ? cloud*NP + (int)(unsigned)(cb[t] & 0xffffffffull) : firstIdx;
        } else {
            for (int t = 0; t < KNBR; ++t) {
                unsigned long long bv = ~0ull; int bp = -1;
                for (int p = lane; p < (int)cnt; p += 32) {
                    unsigned long long vv = cb[p];
                    if (vv < bv) { bv = vv; bp = p; }
                }
                #pragma unroll
                for (int off = 16; off; off >>= 1) {
                    unsigned long long ov = __shfl_xor_sync(0xffffffffu, bv, off);
                    int op = __shfl_xor_sync(0xffffffffu, bp, off);
                    if (ov < bv) { bv = ov; bp = op; }
                }
                if (lane == 0) {
                    d_nbr[base + t] = cloud*NP + (int)(unsigned)(bv & 0xffffffffull);
                    cb[bp] = ~0ull;
                }
                __syncwarp();
            }
        }
        __threadfence();
        __syncwarp();
        if (lane == 0) st_rel(&ballflag[cg], 1);
    }
}

__device__ void g_role(char* smem, const float* __restrict__ x,
                       const float* __restrict__ W1)
{
    float* sW = (float*)smem;            // 64*128
    float* sx = sW + 64*HH;              // 32*64
    int* stask = (int*)(smem + OTASK);
    int tid = threadIdx.x;
    int ndone = 0;

    for (int i = tid; i < 64*HH; i += 256) sW[i] = W1[i];

    for (;;) {
        __syncthreads();
        if (tid == 0) *stask = atomicAdd(&d_sync[0], 1);
        __syncthreads();
        int task = *stask;
        if (task >= NGTASK) break;
        int rbase = task * 32;
        for (int i = tid; i < 32*CIN; i += 256) {
            int r = i >> 6, c = i & 63;
            sx[i] = x[(size_t)(rbase + r)*CIN + c];
        }
        __syncthreads();
        #pragma unroll
        for (int pimg = 0; pimg < 16; ++pimg) {
            int o = tid + pimg*256;
            int r = o >> 7, col = o & 127;
            float acc = 0.0f;
            const float* xr = sx + r*CIN;
            #pragma unroll 16
            for (int c = 0; c < CIN; ++c)
                acc = fmaf(xr[c], sW[c*HH + col], acc);
            g_feat[(size_t)(rbase + r)*HH + col] = acc;
        }
        ++ndone;
    }
    __threadfence();
    __syncthreads();
    if (tid == 0 && ndone) atomicAdd(&d_sync[3], ndone);
}

// ---- GEMM role: bf16-split mma.sync, 3 passes, register max epilogue ----
__device__ void gemm_role(char* smem, const float* __restrict__ pos,
                          const float* __restrict__ W1, const float* __restrict__ b1,
                          const float* __restrict__ W2, const float* __restrict__ b2,
                          float* __restrict__ out)
{
    uint32_t sbase = smem_u32(smem);
    int t = threadIdx.x, w = t >> 5, lane = t & 31;
    int* stask = (int*)(smem + OTASK);

    // A = W2^T bf16 split: Ahi/Alo[m][k], row stride BSTR
    for (int idx = t; idx < HH*HH; idx += 256) {
        int k = idx >> 7, m = idx & 127;
        float v = W2[idx];                         // W2[k][m]
        __nv_bfloat16 hi = __float2bfloat16_rn(v);
        __nv_bfloat16 lo = __float2bfloat16_rn(v - __bfloat162float(hi));
        *(__nv_bfloat16*)(smem + OA_HI + m*BSTR + k*2) = hi;
        *(__nv_bfloat16*)(smem + OA_LO + m*BSTR + k*2) = lo;
    }
    if (t < HH) {
        float4 wb;
        wb.x = b1[t];
        wb.y = W1[64*HH + t]; wb.z = W1[65*HH + t]; wb.w = W1[66*HH + t];
        *(float4*)(smem + OWB + t*16) = wb;
    }
    // gate: all g_feat ready
    if (t == 0) while (ld_acq(&d_sync[3]) < NGTASK) {}
    __syncthreads();

    int g = lane >> 3, r = lane & 7;
    uint32_t aoff = (uint32_t)((16*w + r + (g&1)*8)*BSTR + (g>>1)*16);
    uint32_t boff = (uint32_t)((r + (g&1)*8)*BSTR + (g>>1)*16);
    int rowA = 16*w + (lane >> 2);
    float b2A = b2[rowA], b2B = b2[rowA + 8];

    for (;;) {
        __syncthreads();
        if (t == 0) *stask = atomicAdd(&d_sync[2], 1);
        __syncthreads();
        int tile = *stask;
        if (tile >= NTTASK) break;
        int cloud = tile & 7, lt = tile >> 3;
        int cg0 = cloud*NS + lt*2;

        if (t < 2) { while (ld_acq(&ballflag[cg0 + t]) == 0) {} }
        __syncthreads();

        if (t < HH) {
            int cgx = cg0 + (t >> 6);
            int gj = d_nbr[cgx*KNBR + (t & 63)];
            *(int*)(smem + OGJ + t*4) = gj;
            float4 dp;
            dp.x = pos[(size_t)gj*3+0] - d_ctr[cgx*3+0];
            dp.y = pos[(size_t)gj*3+1] - d_ctr[cgx*3+1];
            dp.z = pos[(size_t)gj*3+2] - d_ctr[cgx*3+2];
            dp.w = 0.f;
            *(float4*)(smem + ODP + t*16) = dp;
        }
        __syncthreads();

        // B build: h1[k][n] bf16 hi/lo; thread = (col n, k-half kh)
        {
            int n = t & 127, kh = t >> 7;
            int gj = *(int*)(smem + OGJ + n*4);
            float4 dp = *(float4*)(smem + ODP + n*16);
            const float4* grow = (const float4*)(g_feat + (size_t)gj*HH + kh*64);
            const float4* swb = (const float4*)(smem + OWB);
            #pragma unroll 4
            for (int q = 0; q < 16; ++q) {
                float4 g4 = __ldg(grow + q);
                int k0 = kh*64 + q*4;
                float gv[4] = {g4.x, g4.y, g4.z, g4.w};
                #pragma unroll
                for (int rr = 0; rr < 4; ++rr) {
                    float4 wb = swb[k0 + rr];
                    float v = gv[rr] + wb.x;
                    v = fmaf(dp.x, wb.y, v);
                    v = fmaf(dp.y, wb.z, v);
                    v = fmaf(dp.z, wb.w, v);
                    float h = fmaxf(v, 0.0f);
                    __nv_bfloat16 hi = __float2bfloat16_rn(h);
                    __nv_bfloat16 lo = __float2bfloat16_rn(h - __bfloat162float(hi));
                    *(__nv_bfloat16*)(smem + OB_HI + (k0+rr)*BSTR + n*2) = hi;
                    *(__nv_bfloat16*)(smem + OB_LO + (k0+rr)*BSTR + n*2) = lo;
                }
            }
        }
        __syncthreads();

        // 3-pass MMA: warp m-stripe [16w,16w+16), 16 n-tiles of 8
        float acc[16][4];
        #pragma unroll
        for (int nt = 0; nt < 16; ++nt)
            #pragma unroll
            for (int i = 0; i < 4; ++i) acc[nt][i] = 0.0f;

        #pragma unroll 1
        for (int kt = 0; kt < 8; ++kt) {
            uint32_t ahk[4], alk[4], bq[32];
            uint32_t abase = sbase + (uint32_t)(32*kt) + aoff;
            ldsm4(ahk[0],ahk[1],ahk[2],ahk[3], abase + OA_HI);
            ldsm4(alk[0],alk[1],alk[2],alk[3], abase + OA_LO);
            uint32_t bbase = sbase + (uint32_t)(16*kt)*BSTR + boff;
            #pragma unroll
            for (int tp = 0; tp < 8; ++tp)
                ldsm4t(bq[4*tp],bq[4*tp+1],bq[4*tp+2],bq[4*tp+3],
                       bbase + OB_HI + (uint32_t)(32*tp));
            #pragma unroll
            for (int nt = 0; nt < 16; ++nt) {
                mma16816(acc[nt], ahk, bq + 2*nt);
                mma16816(acc[nt], alk, bq + 2*nt);
            }
            #pragma unroll
            for (int tp = 0; tp < 8; ++tp)
                ldsm4t(bq[4*tp],bq[4*tp+1],bq[4*tp+2],bq[4*tp+3],
                       bbase + OB_LO + (uint32_t)(32*tp));
            #pragma unroll
            for (int nt = 0; nt < 16; ++nt)
                mma16816(acc[nt], ahk, bq + 2*nt);
        }

        // epilogue: max over n per center, register + shfl only
        float mA0 = -3e38f, mB0 = -3e38f, mA1 = -3e38f, mB1 = -3e38f;
        #pragma unroll
        for (int nt = 0; nt < 8; ++nt) {
            mA0 = fmaxf(mA0, fmaxf(acc[nt][0], acc[nt][1]));
            mB0 = fmaxf(mB0, fmaxf(acc[nt][2], acc[nt][3]));
            mA1 = fmaxf(mA1, fmaxf(acc[nt+8][0], acc[nt+8][1]));
            mB1 = fmaxf(mB1, fmaxf(acc[nt+8][2], acc[nt+8][3]));
        }
        #pragma unroll
        for (int off = 1; off <= 2; off <<= 1) {
            mA0 = fmaxf(mA0, __shfl_xor_sync(0xffffffffu, mA0, off));
            mB0 = fmaxf(mB0, __shfl_xor_sync(0xffffffffu, mB0, off));
            mA1 = fmaxf(mA1, __shfl_xor_sync(0xffffffffu, mA1, off));
            mB1 = fmaxf(mB1, __shfl_xor_sync(0xffffffffu, mB1, off));
        }
        if ((lane & 3) == 0) {
            out[(size_t)cg0*HH + rowA]           = fmaxf(mA0 + b2A, 0.0f);
            out[(size_t)cg0*HH + rowA + 8]       = fmaxf(mB0 + b2B, 0.0f);
            out[(size_t)(cg0+1)*HH + rowA]       = fmaxf(mA1 + b2A, 0.0f);
            out[(size_t)(cg0+1)*HH + rowA + 8]   = fmaxf(mB1 + b2B, 0.0f);
        }
    }
}

// ================= megakernel =================
__global__ __launch_bounds__(256, 1)
void mega(const float* __restrict__ x, const float* __restrict__ pos,
          const float* __restrict__ W1, const float* __restrict__ b1,
          const float* __restrict__ W2, const float* __restrict__ b2,
          float* __restrict__ out, int mode)
{
    extern __shared__ char smem[];
    int bid = blockIdx.x;

    if (bid < BB) {
        fps_role(smem, pos, bid);
    } else if (bid < BB + NBALL) {
        ball_role(smem, pos, out, mode);
    } else {
        g_role(smem, x, W1);
    }
    __syncthreads();
    gemm_role(smem, pos, W1, b1, W2, b2, out);
}

__global__ void k_fill(float* out, int start, int n) {
    int i = blockIdx.x * 256 + threadIdx.x;
    if (i < n) out[start + i] = 0.0f;
}

// ---------------- launch --------------------------------------------------
extern "C" void kernel_launch(void* const* d_in, const int* in_sizes, int n_in,
                              void* d_out, int out_size)
{
    const float* x   = (const float*)d_in[0];
    const float* pos = (const float*)d_in[1];
    const float* W1  = (const float*)d_in[2];
    const float* b1  = (const float*)d_in[3];
    const float* W2  = (const float*)d_in[4];
    const float* b2  = (const float*)d_in[5];
    float* out = (float*)d_out;

    void *p_fps, *p_ball, *p_sync;
    cudaGetSymbolAddress(&p_fps,  fpsflag);
    cudaGetSymbolAddress(&p_ball, ballflag);
    cudaGetSymbolAddress(&p_sync, d_sync);
    cudaMemsetAsync(p_fps,  0, NC*sizeof(int));
    cudaMemsetAsync(p_ball, 0, NC*sizeof(int));
    cudaMemsetAsync(p_sync, 0, 4*sizeof(int));

    cudaFuncSetAttribute(mega, cudaFuncAttributeMaxDynamicSharedMemorySize, SM_TOT);

    int mode = 0;
    int used = NC*HH;
    if (out_size >= NC*HH + NC*3)      { mode |= 1; used = NC*HH + NC*3; }
    if (out_size >= NC*HH + NC*3 + NC) { mode |= 2; used = NC*HH + NC*3 + NC; }

    mega<<<NGRID, 256, SM_TOT>>>(x, pos, W1, b1, W2, b2, out, mode);

    if (out_size > used) {
        int n = out_size - used;
        k_fill<<<(n + 255)/256, 256>>>(out, used, n);
    }
}

// round 8
// speedup vs baseline: 1.0521x; 1.0521x over previous
#include <cuda_runtime.h>
#include <cuda_bf16.h>
#include <cstdint>

#define BB      8
#define NP      4096
#define NS      1024
#define NC      (BB*NS)
#define KNBR    64
#define CIN     64
#define HH      128
#define R2f     0.04f
#define CAP     768
#define NBALL   32
#define NGRID   148
#define NGTASK  1024
#define NTTASK  4096
#define BSTR    272

// ---------------- device scratch ----------------
__device__ float g_feat[BB*NP*HH];
__device__ int   fpsflag[NC];          // idx+1 when ready (payload-in-flag)
__device__ int   ballflag[NC];         // 1 when nbr/ctr ready
__device__ int   d_nbr[NC*KNBR];       // padded to 64 (dup of nbr 0)
__device__ float d_ctr[NC*3];
__device__ int   d_sync[4];            // 0:g_ctr 2:gemm_ctr 3:g_done

// ---------------- helpers ----------------
__device__ __forceinline__ float dist2(float ax,float ay,float az,float bx,float by,float bz){
    float dx = ax-bx, dy = ay-by, dz = az-bz;
    return __fadd_rn(__fadd_rn(__fmul_rn(dx,dx),__fmul_rn(dy,dy)),__fmul_rn(dz,dz));
}
__device__ __forceinline__ uint32_t smem_u32(const void* p){
    uint32_t a;
    asm("{ .reg .u64 t; cvta.to.shared.u64 t, %1; cvt.u32.u64 %0, t; }" : "=r"(a) : "l"(p));
    return a;
}
__device__ __forceinline__ int ld_acq(const int* p){
    int v; asm volatile("ld.acquire.gpu.global.s32 %0, [%1];" : "=r"(v) : "l"(p) : "memory"); return v;
}
__device__ __forceinline__ void st_rel(int* p, int v){
    asm volatile("st.release.gpu.global.s32 [%0], %1;" :: "l"(p), "r"(v) : "memory");
}
__device__ __forceinline__ int ld_rlx(const int* p){
    int v; asm volatile("ld.relaxed.gpu.global.s32 %0, [%1];" : "=r"(v) : "l"(p) : "memory"); return v;
}
__device__ __forceinline__ void st_rlx(int* p, int v){
    asm volatile("st.relaxed.gpu.global.s32 [%0], %1;" :: "l"(p), "r"(v) : "memory");
}
__device__ __forceinline__ void ldsm4(uint32_t& r0,uint32_t& r1,uint32_t& r2,uint32_t& r3,uint32_t a){
    asm volatile("ldmatrix.sync.aligned.m8n8.x4.shared.b16 {%0,%1,%2,%3}, [%4];"
        : "=r"(r0),"=r"(r1),"=r"(r2),"=r"(r3) : "r"(a));
}
__device__ __forceinline__ void ldsm4t(uint32_t& r0,uint32_t& r1,uint32_t& r2,uint32_t& r3,uint32_t a){
    asm volatile("ldmatrix.sync.aligned.m8n8.x4.trans.shared.b16 {%0,%1,%2,%3}, [%4];"
        : "=r"(r0),"=r"(r1),"=r"(r2),"=r"(r3) : "r"(a));
}
__device__ __forceinline__ void mma16816(float* d, const uint32_t* a, const uint32_t* b){
    asm volatile("mma.sync.aligned.m16n8k16.row.col.f32.bf16.bf16.f32 "
        "{%0,%1,%2,%3}, {%4,%5,%6,%7}, {%8,%9}, {%0,%1,%2,%3};"
        : "+f"(d[0]),"+f"(d[1]),"+f"(d[2]),"+f"(d[3])
        : "r"(a[0]),"r"(a[1]),"r"(a[2]),"r"(a[3]), "r"(b[0]),"r"(b[1]));
}

// ---------------- smem layout (GEMM) ----------------
#define OA_HI   0
#define OA_LO   34816
#define OB_HI   69632
#define OB_LO   104448
#define OWB     139264
#define ODP     141312
#define OGJ     143360
#define OTASK   143872
#define SM_TOT  143888

// ---------------- smem layout (FPS) ----------------
#define F_OPX   0                      // float[4096]
#define F_OPY   16384
#define F_OPZ   32768
#define F_SPT   49152                  // float4[4096]: x,y,z,md
#define F_SID   114688                 // int[4096]
#define F_CNT   131072                 // int[257]
#define F_COFF  132100                 // int[256]
#define F_SLOT  133128                 // u64[16]

// ================= FPS role: grid-bucketed, pruned, exact =================
__device__ void fps_role(char* smem, const float* __restrict__ pos, int b)
{
    float* opx = (float*)(smem + F_OPX);
    float* opy = (float*)(smem + F_OPY);
    float* opz = (float*)(smem + F_OPZ);
    float4* spt = (float4*)(smem + F_SPT);
    int*   sid  = (int*)(smem + F_SID);
    int*   cnt  = (int*)(smem + F_CNT);
    int*   coff = (int*)(smem + F_COFF);
    unsigned long long* slots = (unsigned long long*)(smem + F_SLOT);
    int tid = threadIdx.x, lane = tid & 31, warp = tid >> 5;

    const float* pb = pos + (size_t)b*NP*3;
    for (int i = tid; i < NP; i += 256) {
        opx[i] = pb[i*3+0]; opy[i] = pb[i*3+1]; opz[i] = pb[i*3+2];
    }
    if (tid < 257) cnt[tid] = 0;
    __syncthreads();

    // count
    for (int i = tid; i < NP; i += 256) {
        int cx = min(7, (int)(opx[i]*8.0f));
        int cy = min(7, (int)(opy[i]*8.0f));
        int cz = min(3, (int)(opz[i]*4.0f));
        atomicAdd(&cnt[cx*32 + cy*4 + cz], 1);
    }
    __syncthreads();
    if (tid == 0) {
        int run = 0;
        for (int c = 0; c < 256; ++c) { int t = cnt[c]; cnt[c] = run; run += t; }
        cnt[256] = NP;
    }
    __syncthreads();
    if (tid < 256) coff[tid] = cnt[tid];
    __syncthreads();
    // scatter
    for (int i = tid; i < NP; i += 256) {
        int cx = min(7, (int)(opx[i]*8.0f));
        int cy = min(7, (int)(opy[i]*8.0f));
        int cz = min(3, (int)(opz[i]*4.0f));
        int o = atomicAdd(&coff[cx*32 + cy*4 + cz], 1);
        float4 v; v.x = opx[i]; v.y = opy[i]; v.z = opz[i]; v.w = 1e10f;
        spt[o] = v; sid[o] = i;
    }
    if (tid == 0) st_rlx(&fpsflag[b*NS], 1);   // sample 0 = point 0
    __syncthreads();

    // my cell
    int ccx = tid >> 5, ccy = (tid >> 2) & 7, ccz = tid & 3;
    float x0 = ccx*0.125f, x1 = x0 + 0.125f;
    float y0 = ccy*0.125f, y1 = y0 + 0.125f;
    float z0 = ccz*0.25f,  z1 = z0 + 0.25f;
    int beg = cnt[tid], end = cnt[tid+1];
    float smax = (beg < end) ? 1e10f : -1.0f;
    unsigned long long bestp = 0ull;

    int last = 0;
    for (int s = 1; s < NS; ++s) {
        float lx = opx[last], ly = opy[last], lz = opz[last];
        float ddx = fmaxf(fmaxf(x0 - lx, lx - x1), 0.0f);
        float ddy = fmaxf(fmaxf(y0 - ly, ly - y1), 0.0f);
        float ddz = fmaxf(fmaxf(z0 - lz, lz - z1), 0.0f);
        float dmin2 = ddx*ddx + ddy*ddy + ddz*ddz;
        if (!(dmin2 > smax * 1.00001f)) {
            unsigned long long bp = 0ull;
            for (int j = beg; j < end; ++j) {
                float4 v = spt[j];
                float d2 = dist2(v.x, v.y, v.z, lx, ly, lz);
                float m = fminf(v.w, d2);
                spt[j].w = m;
                unsigned long long p =
                    ((unsigned long long)__float_as_uint(m) << 32) |
                    (unsigned)(NP - 1 - sid[j]);
                if (p > bp) bp = p;
            }
            bestp = bp;
            smax = __uint_as_float((unsigned)(bp >> 32));
        }
        unsigned vb = (unsigned)(bestp >> 32);
        unsigned vm = __reduce_max_sync(0xffffffffu, vb);
        unsigned lo = (vb == vm) ? (unsigned)bestp : 0u;
        unsigned lm = __reduce_max_sync(0xffffffffu, lo);
        if (lane == 0)
            slots[(s & 1)*8 + warp] = ((unsigned long long)vm << 32) | lm;
        __syncthreads();
        unsigned long long w = slots[(s & 1)*8];
        #pragma unroll
        for (int k = 1; k < 8; ++k) {
            unsigned long long v = slots[(s & 1)*8 + k];
            if (v > w) w = v;
        }
        last = NP - 1 - (int)(unsigned)(w & 0xffffffffull);
        if (tid == 0) st_rlx(&fpsflag[b*NS + s], last + 1);
    }
}

// ================= ball role: 4 workers per cloud, static tasks =================
__device__ void ball_role(char* smem, const float* __restrict__ pos,
                          float* __restrict__ out, int mode, int wkr)
{
    float* px = (float*)smem;
    float* py = px + NP;
    float* pz = py + NP;
    unsigned long long* cball = (unsigned long long*)(pz + NP);
    int tid = threadIdx.x, lane = tid & 31, wid = tid >> 5;

    int cloud = wkr & 7, lc0 = wkr >> 3;   // lc = lc0, lc0+4, ...

    const float* pb = pos + (size_t)cloud*NP*3;
    for (int i = tid; i < NP; i += 256) {
        px[i] = pb[i*3+0]; py[i] = pb[i*3+1]; pz[i] = pb[i*3+2];
    }
    __syncthreads();

    for (int lc = lc0; lc < 128; lc += 4) {
        int cg = cloud*NS + lc*8 + wid;

        int v = 0;
        if (lane == 0) while ((v = ld_rlx(&fpsflag[cg])) == 0) {}
        v = __shfl_sync(0xffffffffu, v, 0);
        int ci = v - 1;

        float cx = px[ci], cy = py[ci], cz = pz[ci];
        if (lane == 0) {
            d_ctr[cg*3+0] = cx; d_ctr[cg*3+1] = cy; d_ctr[cg*3+2] = cz;
            if (mode & 1) {
                out[NC*HH + cg*3+0] = cx;
                out[NC*HH + cg*3+1] = cy;
                out[NC*HH + cg*3+2] = cz;
            }
            if (mode & 2) out[NC*HH + NC*3 + cg] = (float)cloud;
        }

        unsigned long long* cb = cball + (size_t)wid * CAP;
        unsigned cnt = 0;
        for (int j = lane; j < NP; j += 32) {
            float d2 = dist2(px[j],py[j],pz[j],cx,cy,cz);
            bool in = (d2 <= R2f);
            unsigned m = __ballot_sync(0xffffffffu, in);
            if (in) {
                unsigned o = cnt + __popc(m & ((1u << lane) - 1u));
                if (o < CAP)
                    cb[o] = ((unsigned long long)__float_as_uint(d2) << 32) | (unsigned)j;
            }
            cnt += __popc(m);
        }
        if (cnt > CAP) cnt = CAP;

        int base = cg * KNBR;
        if (cnt <= KNBR) {
            int firstIdx = cloud*NP + (int)(unsigned)(cb[0] & 0xffffffffull);
            for (int t = lane; t < KNBR; t += 32)
                d_nbr[base + t] = (t < (int)cnt)
                    ? cloud*NP + (int)(unsigned)(cb[t] & 0xffffffffull) : firstIdx;
        } else {
            for (int t = 0; t < KNBR; ++t) {
                unsigned long long bv = ~0ull; int bp = -1;
                for (int p = lane; p < (int)cnt; p += 32) {
                    unsigned long long vv = cb[p];
                    if (vv < bv) { bv = vv; bp = p; }
                }
                #pragma unroll
                for (int off = 16; off; off >>= 1) {
                    unsigned long long ov = __shfl_xor_sync(0xffffffffu, bv, off);
                    int op = __shfl_xor_sync(0xffffffffu, bp, off);
                    if (ov < bv) { bv = ov; bp = op; }
                }
                if (lane == 0) {
                    d_nbr[base + t] = cloud*NP + (int)(unsigned)(bv & 0xffffffffull);
                    cb[bp] = ~0ull;
                }
                __syncwarp();
            }
        }
        __threadfence();
        __syncwarp();
        if (lane == 0) st_rel(&ballflag[cg], 1);
    }
}

__device__ void g_role(char* smem, const float* __restrict__ x,
                       const float* __restrict__ W1)
{
    float* sW = (float*)smem;
    float* sx = sW + 64*HH;
    int* stask = (int*)(smem + OTASK);
    int tid = threadIdx.x;
    int ndone = 0;

    for (int i = tid; i < 64*HH; i += 256) sW[i] = W1[i];

    for (;;) {
        __syncthreads();
        if (tid == 0) *stask = atomicAdd(&d_sync[0], 1);
        __syncthreads();
        int task = *stask;
        if (task >= NGTASK) break;
        int rbase = task * 32;
        for (int i = tid; i < 32*CIN; i += 256) {
            int r = i >> 6, c = i & 63;
            sx[i] = x[(size_t)(rbase + r)*CIN + c];
        }
        __syncthreads();
        #pragma unroll
        for (int pimg = 0; pimg < 16; ++pimg) {
            int o = tid + pimg*256;
            int r = o >> 7, col = o & 127;
            float acc = 0.0f;
            const float* xr = sx + r*CIN;
            #pragma unroll 16
            for (int c = 0; c < CIN; ++c)
                acc = fmaf(xr[c], sW[c*HH + col], acc);
            g_feat[(size_t)(rbase + r)*HH + col] = acc;
        }
        ++ndone;
    }
    __threadfence();
    __syncthreads();
    if (tid == 0 && ndone) atomicAdd(&d_sync[3], ndone);
}

// ---- GEMM role: bf16-split mma.sync, 3 passes, register max epilogue ----
__device__ void gemm_role(char* smem, const float* __restrict__ pos,
                          const float* __restrict__ W1, const float* __restrict__ b1,
                          const float* __restrict__ W2, const float* __restrict__ b2,
                          float* __restrict__ out)
{
    uint32_t sbase = smem_u32(smem);
    int t = threadIdx.x, w = t >> 5, lane = t & 31;
    int* stask = (int*)(smem + OTASK);

    for (int idx = t; idx < HH*HH; idx += 256) {
        int k = idx >> 7, m = idx & 127;
        float v = W2[idx];
        __nv_bfloat16 hi = __float2bfloat16_rn(v);
        __nv_bfloat16 lo = __float2bfloat16_rn(v - __bfloat162float(hi));
        *(__nv_bfloat16*)(smem + OA_HI + m*BSTR + k*2) = hi;
        *(__nv_bfloat16*)(smem + OA_LO + m*BSTR + k*2) = lo;
    }
    if (t < HH) {
        float4 wb;
        wb.x = b1[t];
        wb.y = W1[64*HH + t]; wb.z = W1[65*HH + t]; wb.w = W1[66*HH + t];
        *(float4*)(smem + OWB + t*16) = wb;
    }
    if (t == 0) while (ld_acq(&d_sync[3]) < NGTASK) {}
    __syncthreads();

    int g = lane >> 3, r = lane & 7;
    uint32_t aoff = (uint32_t)((16*w + r + (g&1)*8)*BSTR + (g>>1)*16);
    uint32_t boff = (uint32_t)((r + (g&1)*8)*BSTR + (g>>1)*16);
    int rowA = 16*w + (lane >> 2);
    float b2A = b2[rowA], b2B = b2[rowA + 8];

    for (;;) {
        __syncthreads();
        if (t == 0) *stask = atomicAdd(&d_sync[2], 1);
        __syncthreads();
        int tile = *stask;
        if (tile >= NTTASK) break;
        int cloud = tile & 7, lt = tile >> 3;
        int cg0 = cloud*NS + lt*2;

        if (t < 2) { while (ld_acq(&ballflag[cg0 + t]) == 0) {} }
        __syncthreads();

        if (t < HH) {
            int cgx = cg0 + (t >> 6);
            int gj = d_nbr[cgx*KNBR + (t & 63)];
            *(int*)(smem + OGJ + t*4) = gj;
            float4 dp;
            dp.x = pos[(size_t)gj*3+0] - d_ctr[cgx*3+0];
            dp.y = pos[(size_t)gj*3+1] - d_ctr[cgx*3+1];
            dp.z = pos[(size_t)gj*3+2] - d_ctr[cgx*3+2];
            dp.w = 0.f;
            *(float4*)(smem + ODP + t*16) = dp;
        }
        __syncthreads();

        {
            int n = t & 127, kh = t >> 7;
            int gj = *(int*)(smem + OGJ + n*4);
            float4 dp = *(float4*)(smem + ODP + n*16);
            const float4* grow = (const float4*)(g_feat + (size_t)gj*HH + kh*64);
            const float4* swb = (const float4*)(smem + OWB);
            #pragma unroll 4
            for (int q = 0; q < 16; ++q) {
                float4 g4 = __ldg(grow + q);
                int k0 = kh*64 + q*4;
                float gv[4] = {g4.x, g4.y, g4.z, g4.w};
                #pragma unroll
                for (int rr = 0; rr < 4; ++rr) {
                    float4 wb = swb[k0 + rr];
                    float v = gv[rr] + wb.x;
                    v = fmaf(dp.x, wb.y, v);
                    v = fmaf(dp.y, wb.z, v);
                    v = fmaf(dp.z, wb.w, v);
                    float h = fmaxf(v, 0.0f);
                    __nv_bfloat16 hi = __float2bfloat16_rn(h);
                    __nv_bfloat16 lo = __float2bfloat16_rn(h - __bfloat162float(hi));
                    *(__nv_bfloat16*)(smem + OB_HI + (k0+rr)*BSTR + n*2) = hi;
                    *(__nv_bfloat16*)(smem + OB_LO + (k0+rr)*BSTR + n*2) = lo;
                }
            }
        }
        __syncthreads();

        float acc[16][4];
        #pragma unroll
        for (int nt = 0; nt < 16; ++nt)
            #pragma unroll
            for (int i = 0; i < 4; ++i) acc[nt][i] = 0.0f;

        #pragma unroll 1
        for (int kt = 0; kt < 8; ++kt) {
            uint32_t ahk[4], alk[4], bq[32];
            uint32_t abase = sbase + (uint32_t)(32*kt) + aoff;
            ldsm4(ahk[0],ahk[1],ahk[2],ahk[3], abase + OA_HI);
            ldsm4(alk[0],alk[1],alk[2],alk[3], abase + OA_LO);
            uint32_t bbase = sbase + (uint32_t)(16*kt)*BSTR + boff;
            #pragma unroll
            for (int tp = 0; tp < 8; ++tp)
                ldsm4t(bq[4*tp],bq[4*tp+1],bq[4*tp+2],bq[4*tp+3],
                       bbase + OB_HI + (uint32_t)(32*tp));
            #pragma unroll
            for (int nt = 0; nt < 16; ++nt) {
                mma16816(acc[nt], ahk, bq + 2*nt);
                mma16816(acc[nt], alk, bq + 2*nt);
            }
            #pragma unroll
            for (int tp = 0; tp < 8; ++tp)
                ldsm4t(bq[4*tp],bq[4*tp+1],bq[4*tp+2],bq[4*tp+3],
                       bbase + OB_LO + (uint32_t)(32*tp));
            #pragma unroll
            for (int nt = 0; nt < 16; ++nt)
                mma16816(acc[nt], ahk, bq + 2*nt);
        }

        float mA0 = -3e38f, mB0 = -3e38f, mA1 = -3e38f, mB1 = -3e38f;
        #pragma unroll
        for (int nt = 0; nt < 8; ++nt) {
            mA0 = fmaxf(mA0, fmaxf(acc[nt][0], acc[nt][1]));
            mB0 = fmaxf(mB0, fmaxf(acc[nt][2], acc[nt][3]));
            mA1 = fmaxf(mA1, fmaxf(acc[nt+8][0], acc[nt+8][1]));
            mB1 = fmaxf(mB1, fmaxf(acc[nt+8][2], acc[nt+8][3]));
        }
        #pragma unroll
        for (int off = 1; off <= 2; off <<= 1) {
            mA0 = fmaxf(mA0, __shfl_xor_sync(0xffffffffu, mA0, off));
            mB0 = fmaxf(mB0, __shfl_xor_sync(0xffffffffu, mB0, off));
            mA1 = fmaxf(mA1, __shfl_xor_sync(0xffffffffu, mA1, off));
            mB1 = fmaxf(mB1, __shfl_xor_sync(0xffffffffu, mB1, off));
        }
        if ((lane & 3) == 0) {
            out[(size_t)cg0*HH + rowA]           = fmaxf(mA0 + b2A, 0.0f);
            out[(size_t)cg0*HH + rowA + 8]       = fmaxf(mB0 + b2B, 0.0f);
            out[(size_t)(cg0+1)*HH + rowA]       = fmaxf(mA1 + b2A, 0.0f);
            out[(size_t)(cg0+1)*HH + rowA + 8]   = fmaxf(mB1 + b2B, 0.0f);
        }
    }
}

// ================= megakernel =================
__global__ __launch_bounds__(256, 1)
void mega(const float* __restrict__ x, const float* __restrict__ pos,
          const float* __restrict__ W1, const float* __restrict__ b1,
          const float* __restrict__ W2, const float* __restrict__ b2,
          float* __restrict__ out, int mode)
{
    extern __shared__ char smem[];
    int bid = blockIdx.x;

    if (bid < BB) {
        fps_role(smem, pos, bid);
    } else if (bid < BB + NBALL) {
        ball_role(smem, pos, out, mode, bid - BB);
    } else {
        g_role(smem, x, W1);
    }
    __syncthreads();
    gemm_role(smem, pos, W1, b1, W2, b2, out);
}

__global__ void k_fill(float* out, int start, int n) {
    int i = blockIdx.x * 256 + threadIdx.x;
    if (i < n) out[start + i] = 0.0f;
}

// ---------------- launch --------------------------------------------------
extern "C" void kernel_launch(void* const* d_in, const int* in_sizes, int n_in,
                              void* d_out, int out_size)
{
    const float* x   = (const float*)d_in[0];
    const float* pos = (const float*)d_in[1];
    const float* W1  = (const float*)d_in[2];
    const float* b1  = (const float*)d_in[3];
    const float* W2  = (const float*)d_in[4];
    const float* b2  = (const float*)d_in[5];
    float* out = (float*)d_out;

    void *p_fps, *p_ball, *p_sync;
    cudaGetSymbolAddress(&p_fps,  fpsflag);
    cudaGetSymbolAddress(&p_ball, ballflag);
    cudaGetSymbolAddress(&p_sync, d_sync);
    cudaMemsetAsync(p_fps,  0, NC*sizeof(int));
    cudaMemsetAsync(p_ball, 0, NC*sizeof(int));
    cudaMemsetAsync(p_sync, 0, 4*sizeof(int));

    cudaFuncSetAttribute(mega, cudaFuncAttributeMaxDynamicSharedMemorySize, SM_TOT);

    int mode = 0;
    int used = NC*HH;
    if (out_size >= NC*HH + NC*3)      { mode |= 1; used = NC*HH + NC*3; }
    if (out_size >= NC*HH + NC*3 + NC) { mode |= 2; used = NC*HH + NC*3 + NC; }

    mega<<<NGRID, 256, SM_TOT>>>(x, pos, W1, b1, W2, b2, out, mode);

    if (out_size > used) {
        int n = out_size - used;
        k_fill<<<(n + 255)/256, 256>>>(out, used, n);
    }
}

// round 10
// speedup vs baseline: 1.2380x; 1.1767x over previous
#include <cuda_runtime.h>
#include <cuda_bf16.h>
#include <cstdint>

#define BB      8
#define NP      4096
#define NS      1024
#define NC      (BB*NS)
#define KNBR    64
#define CIN     64
#define HH      128
#define R2f     0.04f
#define CAP     768
#define NBALL   32
#define NGRID   148
#define NGTASK  1024
#define NTTASK  4096
#define BSTR    272

// ---------------- device scratch ----------------
__device__ float g_feat[BB*NP*HH];
__device__ int   fpsflag[NC];          // idx+1 when ready (payload-in-flag)
__device__ int   ballflag[NC];         // 1 when nbr/ctr ready
__device__ int   d_nbr[NC*KNBR];       // padded to 64
__device__ float d_ctr[NC*3];
__device__ int   d_sync[4];            // 0:g_ctr 2:gemm_ctr 3:g_done

// ---------------- helpers ----------------
__device__ __forceinline__ float dist2(float ax,float ay,float az,float bx,float by,float bz){
    float dx = ax-bx, dy = ay-by, dz = az-bz;
    return __fadd_rn(__fadd_rn(__fmul_rn(dx,dx),__fmul_rn(dy,dy)),__fmul_rn(dz,dz));
}
__device__ __forceinline__ uint32_t smem_u32(const void* p){
    uint32_t a;
    asm("{ .reg .u64 t; cvta.to.shared.u64 t, %1; cvt.u32.u64 %0, t; }" : "=r"(a) : "l"(p));
    return a;
}
__device__ __forceinline__ int ld_acq(const int* p){
    int v; asm volatile("ld.acquire.gpu.global.s32 %0, [%1];" : "=r"(v) : "l"(p) : "memory"); return v;
}
__device__ __forceinline__ void st_rel(int* p, int v){
    asm volatile("st.release.gpu.global.s32 [%0], %1;" :: "l"(p), "r"(v) : "memory");
}
__device__ __forceinline__ int ld_rlx(const int* p){
    int v; asm volatile("ld.relaxed.gpu.global.s32 %0, [%1];" : "=r"(v) : "l"(p) : "memory"); return v;
}
__device__ __forceinline__ void st_rlx(int* p, int v){
    asm volatile("st.relaxed.gpu.global.s32 [%0], %1;" :: "l"(p), "r"(v) : "memory");
}
__device__ __forceinline__ void ldsm4(uint32_t& r0,uint32_t& r1,uint32_t& r2,uint32_t& r3,uint32_t a){
    asm volatile("ldmatrix.sync.aligned.m8n8.x4.shared.b16 {%0,%1,%2,%3}, [%4];"
        : "=r"(r0),"=r"(r1),"=r"(r2),"=r"(r3) : "r"(a));
}
__device__ __forceinline__ void ldsm4t(uint32_t& r0,uint32_t& r1,uint32_t& r2,uint32_t& r3,uint32_t a){
    asm volatile("ldmatrix.sync.aligned.m8n8.x4.trans.shared.b16 {%0,%1,%2,%3}, [%4];"
        : "=r"(r0),"=r"(r1),"=r"(r2),"=r"(r3) : "r"(a));
}
__device__ __forceinline__ void mma16816(float* d, const uint32_t* a, const uint32_t* b){
    asm volatile("mma.sync.aligned.m16n8k16.row.col.f32.bf16.bf16.f32 "
        "{%0,%1,%2,%3}, {%4,%5,%6,%7}, {%8,%9}, {%0,%1,%2,%3};"
        : "+f"(d[0]),"+f"(d[1]),"+f"(d[2]),"+f"(d[3])
        : "r"(a[0]),"r"(a[1]),"r"(a[2]),"r"(a[3]), "r"(b[0]),"r"(b[1]));
}

// ---------------- smem layout (GEMM) ----------------
#define OA_HI   0
#define OA_LO   34816
#define OB_HI   69632
#define OB_LO   104448
#define OWB     139264
#define ODP     141312
#define OGJ     143360
#define OTASK   143872
#define SM_TOT  143888

// ---------------- smem layout (ball extra) ----------------
#define B_CNTR  98304                  // int[16]: per-warp {strict, tie} counters

// ---------------- smem layout (FPS) ----------------
#define F_OPX   0
#define F_OPY   16384
#define F_OPZ   32768
#define F_SPT   49152
#define F_SID   114688
#define F_CNT   131072
#define F_COFF  132100
#define F_SLOT  133128

// ================= FPS role: grid-bucketed, pruned, exact =================
__device__ void fps_role(char* smem, const float* __restrict__ pos, int b)
{
    float* opx = (float*)(smem + F_OPX);
    float* opy = (float*)(smem + F_OPY);
    float* opz = (float*)(smem + F_OPZ);
    float4* spt = (float4*)(smem + F_SPT);
    int*   sid  = (int*)(smem + F_SID);
    int*   cnt  = (int*)(smem + F_CNT);
    int*   coff = (int*)(smem + F_COFF);
    unsigned long long* slots = (unsigned long long*)(smem + F_SLOT);
    int tid = threadIdx.x, lane = tid & 31, warp = tid >> 5;

    const float* pb = pos + (size_t)b*NP*3;
    for (int i = tid; i < NP; i += 256) {
        opx[i] = pb[i*3+0]; opy[i] = pb[i*3+1]; opz[i] = pb[i*3+2];
    }
    if (tid < 257) cnt[tid] = 0;
    __syncthreads();

    for (int i = tid; i < NP; i += 256) {
        int cx = min(7, (int)(opx[i]*8.0f));
        int cy = min(7, (int)(opy[i]*8.0f));
        int cz = min(3, (int)(opz[i]*4.0f));
        atomicAdd(&cnt[cx*32 + cy*4 + cz], 1);
    }
    __syncthreads();
    if (tid == 0) {
        int run = 0;
        for (int c = 0; c < 256; ++c) { int t = cnt[c]; cnt[c] = run; run += t; }
        cnt[256] = NP;
    }
    __syncthreads();
    if (tid < 256) coff[tid] = cnt[tid];
    __syncthreads();
    for (int i = tid; i < NP; i += 256) {
        int cx = min(7, (int)(opx[i]*8.0f));
        int cy = min(7, (int)(opy[i]*8.0f));
        int cz = min(3, (int)(opz[i]*4.0f));
        int o = atomicAdd(&coff[cx*32 + cy*4 + cz], 1);
        float4 v; v.x = opx[i]; v.y = opy[i]; v.z = opz[i]; v.w = 1e10f;
        spt[o] = v; sid[o] = i;
    }
    if (tid == 0) st_rlx(&fpsflag[b*NS], 1);
    __syncthreads();

    int ccx = tid >> 5, ccy = (tid >> 2) & 7, ccz = tid & 3;
    float x0 = ccx*0.125f, x1 = x0 + 0.125f;
    float y0 = ccy*0.125f, y1 = y0 + 0.125f;
    float z0 = ccz*0.25f,  z1 = z0 + 0.25f;
    int beg = cnt[tid], end = cnt[tid+1];
    float smax = (beg < end) ? 1e10f : -1.0f;
    unsigned long long bestp = 0ull;

    int last = 0;
    for (int s = 1; s < NS; ++s) {
        float lx = opx[last], ly = opy[last], lz = opz[last];
        float ddx = fmaxf(fmaxf(x0 - lx, lx - x1), 0.0f);
        float ddy = fmaxf(fmaxf(y0 - ly, ly - y1), 0.0f);
        float ddz = fmaxf(fmaxf(z0 - lz, lz - z1), 0.0f);
        float dmin2 = ddx*ddx + ddy*ddy + ddz*ddz;
        if (!(dmin2 > smax * 1.00001f)) {
            unsigned long long bp = 0ull;
            for (int j = beg; j < end; ++j) {
                float4 v = spt[j];
                float d2 = dist2(v.x, v.y, v.z, lx, ly, lz);
                float m = fminf(v.w, d2);
                spt[j].w = m;
                unsigned long long p =
                    ((unsigned long long)__float_as_uint(m) << 32) |
                    (unsigned)(NP - 1 - sid[j]);
                if (p > bp) bp = p;
            }
            bestp = bp;
            smax = __uint_as_float((unsigned)(bp >> 32));
        }
        unsigned vb = (unsigned)(bestp >> 32);
        unsigned vm = __reduce_max_sync(0xffffffffu, vb);
        unsigned lo = (vb == vm) ? (unsigned)bestp : 0u;
        unsigned lm = __reduce_max_sync(0xffffffffu, lo);
        if (lane == 0)
            slots[(s & 1)*8 + warp] = ((unsigned long long)vm << 32) | lm;
        __syncthreads();
        unsigned long long w = slots[(s & 1)*8];
        #pragma unroll
        for (int k = 1; k < 8; ++k) {
            unsigned long long v = slots[(s & 1)*8 + k];
            if (v > w) w = v;
        }
        last = NP - 1 - (int)(unsigned)(w & 0xffffffffull);
        if (tid == 0) st_rlx(&fpsflag[b*NS + s], last + 1);
    }
}

// ================= ball role: hardened threshold select =================
__device__ void ball_role(char* smem, const float* __restrict__ pos,
                          float* __restrict__ out, int mode, int wkr)
{
    float* px = (float*)smem;
    float* py = px + NP;
    float* pz = py + NP;
    unsigned long long* cball = (unsigned long long*)(pz + NP);
    int* wcnt = (int*)(smem + B_CNTR);
    int tid = threadIdx.x, lane = tid & 31, wid = tid >> 5;

    int cloud = wkr & 7, lc0 = wkr >> 3;

    const float* pb = pos + (size_t)cloud*NP*3;
    for (int i = tid; i < NP; i += 256) {
        px[i] = pb[i*3+0]; py[i] = pb[i*3+1]; pz[i] = pb[i*3+2];
    }
    __syncthreads();

    for (int lc = lc0; lc < 128; lc += 4) {
        int cg = cloud*NS + lc*8 + wid;

        int v = 0;
        if (lane == 0) while ((v = ld_rlx(&fpsflag[cg])) == 0) {}
        v = __shfl_sync(0xffffffffu, v, 0);
        int ci = v - 1;

        float cx = px[ci], cy = py[ci], cz = pz[ci];
        if (lane == 0) {
            d_ctr[cg*3+0] = cx; d_ctr[cg*3+1] = cy; d_ctr[cg*3+2] = cz;
            if (mode & 1) {
                out[NC*HH + cg*3+0] = cx;
                out[NC*HH + cg*3+1] = cy;
                out[NC*HH + cg*3+2] = cz;
            }
            if (mode & 2) out[NC*HH + NC*3 + cg] = (float)cloud;
        }

        unsigned long long* cb = cball + (size_t)wid * CAP;
        unsigned cnt = 0;
        for (int j = lane; j < NP; j += 32) {
            float d2 = dist2(px[j],py[j],pz[j],cx,cy,cz);
            bool in = (d2 <= R2f);
            unsigned m = __ballot_sync(0xffffffffu, in);
            if (in) {
                unsigned o = cnt + __popc(m & ((1u << lane) - 1u));
                if (o < CAP)
                    cb[o] = ((unsigned long long)__float_as_uint(d2) << 32) | (unsigned)j;
            }
            cnt += __popc(m);
        }
        if (cnt > CAP) cnt = CAP;

        int base = cg * KNBR;
        int padIdx = cloud*NP + ci;      // center itself: always a valid neighbor
        if (cnt <= KNBR) {
            for (int t = lane; t < KNBR; t += 32)
                d_nbr[base + t] = (t < (int)cnt)
                    ? cloud*NP + (int)(unsigned)(cb[t] & 0xffffffffull) : padIdx;
            if ((int)cnt < 1 && lane == 0) d_nbr[base] = padIdx;  // unreachable guard
        } else if (cnt <= 256) {
            // ---- binary-search threshold T = 64th-smallest d2 bits ----
            unsigned h32[8], l32[8];
            #pragma unroll
            for (int q = 0; q < 8; ++q) {
                int p = lane + q*32;
                unsigned long long vv = (p < (int)cnt) ? cb[p] : ~0ull;
                h32[q] = (unsigned)(vv >> 32);
                l32[q] = (unsigned)vv;
            }
            unsigned slo = 0u, shi = 0x3D23D70Bu;   // bits(0.04f)+1
            while (shi > slo) {
                unsigned mid = (slo + shi) >> 1;
                int c = 0;
                #pragma unroll
                for (int q = 0; q < 8; ++q) c += (h32[q] <= mid) ? 1 : 0;
                c = __reduce_add_sync(0xffffffffu, c);
                if (c >= KNBR) shi = mid; else slo = mid + 1;
            }
            unsigned T = slo;

            // ---- emit via clamped per-warp atomic counters ----
            int* wc = wcnt + wid*2;
            if (lane == 0) { wc[0] = 0; wc[1] = 0; }
            __syncwarp();
            unsigned long long* tb = cb + 512;   // 256 tie slots
            #pragma unroll
            for (int q = 0; q < 8; ++q) {
                if (h32[q] < T) {
                    int p = atomicAdd(&wc[0], 1);
                    if (p < KNBR) d_nbr[base + p] = cloud*NP + (int)l32[q];
                } else if (h32[q] == T) {
                    int p = atomicAdd(&wc[1], 1);
                    if (p < 256) tb[p] = ((unsigned long long)T << 32) | l32[q];
                }
            }
            __syncwarp();
            int ns = wc[0]; if (ns > KNBR) ns = KNBR;
            int tc = wc[1]; if (tc > 256) tc = 256;
            int r = KNBR - ns;
            if (r > tc) r = tc;
            if (r < 0) r = 0;

            // r rounds of argmin over ties (lowest idx first)
            for (int t = 0; t < r; ++t) {
                unsigned long long bv = ~0ull; int bp = 0;
                for (int p = lane; p < tc; p += 32) {
                    unsigned long long vv = tb[p];
                    if (vv < bv) { bv = vv; bp = p; }
                }
                #pragma unroll
                for (int off = 16; off; off >>= 1) {
                    unsigned long long ov = __shfl_xor_sync(0xffffffffu, bv, off);
                    int op = __shfl_xor_sync(0xffffffffu, bp, off);
                    if (ov < bv) { bv = ov; bp = op; }
                }
                if (lane == 0 && bv != ~0ull) {
                    d_nbr[base + ns + t] = cloud*NP + (int)(unsigned)(bv & 0xffffffffull);
                    tb[bp] = ~0ull;
                }
                __syncwarp();
            }
            // defensive pad (no-op when logic correct)
            for (int t = ns + r + lane; t < KNBR; t += 32)
                d_nbr[base + t] = padIdx;
        } else {
            // fallback: iterative 64-round argmin (cnt > 256, ~never)
            for (int t = 0; t < KNBR; ++t) {
                unsigned long long bv = ~0ull; int bp = 0;
                for (int p = lane; p < (int)cnt; p += 32) {
                    unsigned long long vv = cb[p];
                    if (vv < bv) { bv = vv; bp = p; }
                }
                #pragma unroll
                for (int off = 16; off; off >>= 1) {
                    unsigned long long ov = __shfl_xor_sync(0xffffffffu, bv, off);
                    int op = __shfl_xor_sync(0xffffffffu, bp, off);
                    if (ov < bv) { bv = ov; bp = op; }
                }
                if (lane == 0) {
                    d_nbr[base + t] = cloud*NP + (int)(unsigned)(bv & 0xffffffffull);
                    cb[bp] = ~0ull;
                }
                __syncwarp();
            }
        }
        __threadfence();
        __syncwarp();
        if (lane == 0) st_rel(&ballflag[cg], 1);
    }
}

__device__ void g_role(char* smem, const float* __restrict__ x,
                       const float* __restrict__ W1)
{
    float* sW = (float*)smem;
    float* sx = sW + 64*HH;
    int* stask = (int*)(smem + OTASK);
    int tid = threadIdx.x;
    int ndone = 0;

    for (int i = tid; i < 64*HH; i += 256) sW[i] = W1[i];

    for (;;) {
        __syncthreads();
        if (tid == 0) *stask = atomicAdd(&d_sync[0], 1);
        __syncthreads();
        int task = *stask;
        if (task >= NGTASK) break;
        int rbase = task * 32;
        for (int i = tid; i < 32*CIN; i += 256) {
            int r = i >> 6, c = i & 63;
            sx[i] = x[(size_t)(rbase + r)*CIN + c];
        }
        __syncthreads();
        #pragma unroll
        for (int pimg = 0; pimg < 16; ++pimg) {
            int o = tid + pimg*256;
            int r = o >> 7, col = o & 127;
            float acc = 0.0f;
            const float* xr = sx + r*CIN;
            #pragma unroll 16
            for (int c = 0; c < CIN; ++c)
                acc = fmaf(xr[c], sW[c*HH + col], acc);
            g_feat[(size_t)(rbase + r)*HH + col] = acc;
        }
        ++ndone;
    }
    __threadfence();
    __syncthreads();
    if (tid == 0 && ndone) atomicAdd(&d_sync[3], ndone);
}

// ---- GEMM role: bf16-split mma.sync, 3 passes, register max epilogue ----
__device__ void gemm_role(char* smem, const float* __restrict__ pos,
                          const float* __restrict__ W1, const float* __restrict__ b1,
                          const float* __restrict__ W2, const float* __restrict__ b2,
                          float* __restrict__ out)
{
    uint32_t sbase = smem_u32(smem);
    int t = threadIdx.x, w = t >> 5, lane = t & 31;
    int* stask = (int*)(smem + OTASK);

    for (int idx = t; idx < HH*HH; idx += 256) {
        int k = idx >> 7, m = idx & 127;
        float v = W2[idx];
        __nv_bfloat16 hi = __float2bfloat16_rn(v);
        __nv_bfloat16 lo = __float2bfloat16_rn(v - __bfloat162float(hi));
        *(__nv_bfloat16*)(smem + OA_HI + m*BSTR + k*2) = hi;
        *(__nv_bfloat16*)(smem + OA_LO + m*BSTR + k*2) = lo;
    }
    if (t < HH) {
        float4 wb;
        wb.x = b1[t];
        wb.y = W1[64*HH + t]; wb.z = W1[65*HH + t]; wb.w = W1[66*HH + t];
        *(float4*)(smem + OWB + t*16) = wb;
    }
    if (t == 0) while (ld_acq(&d_sync[3]) < NGTASK) {}
    __syncthreads();

    int g = lane >> 3, r = lane & 7;
    uint32_t aoff = (uint32_t)((16*w + r + (g&1)*8)*BSTR + (g>>1)*16);
    uint32_t boff = (uint32_t)((r + (g&1)*8)*BSTR + (g>>1)*16);
    int rowA = 16*w + (lane >> 2);
    float b2A = b2[rowA], b2B = b2[rowA + 8];

    for (;;) {
        __syncthreads();
        if (t == 0) *stask = atomicAdd(&d_sync[2], 1);
        __syncthreads();
        int tile = *stask;
        if (tile >= NTTASK) break;
        int cloud = tile & 7, lt = tile >> 3;
        int cg0 = cloud*NS + lt*2;

        if (t < 2) { while (ld_acq(&ballflag[cg0 + t]) == 0) {} }
        __syncthreads();

        if (t < HH) {
            int cgx = cg0 + (t >> 6);
            int gj = d_nbr[cgx*KNBR + (t & 63)];
            *(int*)(smem + OGJ + t*4) = gj;
            float4 dp;
            dp.x = pos[(size_t)gj*3+0] - d_ctr[cgx*3+0];
            dp.y = pos[(size_t)gj*3+1] - d_ctr[cgx*3+1];
            dp.z = pos[(size_t)gj*3+2] - d_ctr[cgx*3+2];
            dp.w = 0.f;
            *(float4*)(smem + ODP + t*16) = dp;
        }
        __syncthreads();

        {
            int n = t & 127, kh = t >> 7;
            int gj = *(int*)(smem + OGJ + n*4);
            float4 dp = *(float4*)(smem + ODP + n*16);
            const float4* grow = (const float4*)(g_feat + (size_t)gj*HH + kh*64);
            const float4* swb = (const float4*)(smem + OWB);
            #pragma unroll 4
            for (int q = 0; q < 16; ++q) {
                float4 g4 = __ldg(grow + q);
                int k0 = kh*64 + q*4;
                float gv[4] = {g4.x, g4.y, g4.z, g4.w};
                #pragma unroll
                for (int rr = 0; rr < 4; ++rr) {
                    float4 wb = swb[k0 + rr];
                    float v = gv[rr] + wb.x;
                    v = fmaf(dp.x, wb.y, v);
                    v = fmaf(dp.y, wb.z, v);
                    v = fmaf(dp.z, wb.w, v);
                    float h = fmaxf(v, 0.0f);
                    __nv_bfloat16 hi = __float2bfloat16_rn(h);
                    __nv_bfloat16 lo = __float2bfloat16_rn(h - __bfloat162float(hi));
                    *(__nv_bfloat16*)(smem + OB_HI + (k0+rr)*BSTR + n*2) = hi;
                    *(__nv_bfloat16*)(smem + OB_LO + (k0+rr)*BSTR + n*2) = lo;
                }
            }
        }
        __syncthreads();

        float acc[16][4];
        #pragma unroll
        for (int nt = 0; nt < 16; ++nt)
            #pragma unroll
            for (int i = 0; i < 4; ++i) acc[nt][i] = 0.0f;

        #pragma unroll 1
        for (int kt = 0; kt < 8; ++kt) {
            uint32_t ahk[4], alk[4], bq[32];
            uint32_t abase = sbase + (uint32_t)(32*kt) + aoff;
            ldsm4(ahk[0],ahk[1],ahk[2],ahk[3], abase + OA_HI);
            ldsm4(alk[0],alk[1],alk[2],alk[3], abase + OA_LO);
            uint32_t bbase = sbase + (uint32_t)(16*kt)*BSTR + boff;
            #pragma unroll
            for (int tp = 0; tp < 8; ++tp)
                ldsm4t(bq[4*tp],bq[4*tp+1],bq[4*tp+2],bq[4*tp+3],
                       bbase + OB_HI + (uint32_t)(32*tp));
            #pragma unroll
            for (int nt = 0; nt < 16; ++nt) {
                mma16816(acc[nt], ahk, bq + 2*nt);
                mma16816(acc[nt], alk, bq + 2*nt);
            }
            #pragma unroll
            for (int tp = 0; tp < 8; ++tp)
                ldsm4t(bq[4*tp],bq[4*tp+1],bq[4*tp+2],bq[4*tp+3],
                       bbase + OB_LO + (uint32_t)(32*tp));
            #pragma unroll
            for (int nt = 0; nt < 16; ++nt)
                mma16816(acc[nt], ahk, bq + 2*nt);
        }

        float mA0 = -3e38f, mB0 = -3e38f, mA1 = -3e38f, mB1 = -3e38f;
        #pragma unroll
        for (int nt = 0; nt < 8; ++nt) {
            mA0 = fmaxf(mA0, fmaxf(acc[nt][0], acc[nt][1]));
            mB0 = fmaxf(mB0, fmaxf(acc[nt][2], acc[nt][3]));
            mA1 = fmaxf(mA1, fmaxf(acc[nt+8][0], acc[nt+8][1]));
            mB1 = fmaxf(mB1, fmaxf(acc[nt+8][2], acc[nt+8][3]));
        }
        #pragma unroll
        for (int off = 1; off <= 2; off <<= 1) {
            mA0 = fmaxf(mA0, __shfl_xor_sync(0xffffffffu, mA0, off));
            mB0 = fmaxf(mB0, __shfl_xor_sync(0xffffffffu, mB0, off));
            mA1 = fmaxf(mA1, __shfl_xor_sync(0xffffffffu, mA1, off));
            mB1 = fmaxf(mB1, __shfl_xor_sync(0xffffffffu, mB1, off));
        }
        if ((lane & 3) == 0) {
            out[(size_t)cg0*HH + rowA]           = fmaxf(mA0 + b2A, 0.0f);
            out[(size_t)cg0*HH + rowA + 8]       = fmaxf(mB0 + b2B, 0.0f);
            out[(size_t)(cg0+1)*HH + rowA]       = fmaxf(mA1 + b2A, 0.0f);
            out[(size_t)(cg0+1)*HH + rowA + 8]   = fmaxf(mB1 + b2B, 0.0f);
        }
    }
}

// ================= megakernel =================
__global__ __launch_bounds__(256, 1)
void mega(const float* __restrict__ x, const float* __restrict__ pos,
          const float* __restrict__ W1, const float* __restrict__ b1,
          const float* __restrict__ W2, const float* __restrict__ b2,
          float* __restrict__ out, int mode)
{
    extern __shared__ char smem[];
    int bid = blockIdx.x;

    if (bid < BB) {
        fps_role(smem, pos, bid);
    } else if (bid < BB + NBALL) {
        ball_role(smem, pos, out, mode, bid - BB);
    } else {
        g_role(smem, x, W1);
    }
    __syncthreads();
    gemm_role(smem, pos, W1, b1, W2, b2, out);
}

__global__ void k_fill(float* out, int start, int n) {
    int i = blockIdx.x * 256 + threadIdx.x;
    if (i < n) out[start + i] = 0.0f;
}

// ---------------- launch --------------------------------------------------
extern "C" void kernel_launch(void* const* d_in, const int* in_sizes, int n_in,
                              void* d_out, int out_size)
{
    const float* x   = (const float*)d_in[0];
    const float* pos = (const float*)d_in[1];
    const float* W1  = (const float*)d_in[2];
    const float* b1  = (const float*)d_in[3];
    const float* W2  = (const float*)d_in[4];
    const float* b2  = (const float*)d_in[5];
    float* out = (float*)d_out;

    void *p_fps, *p_ball, *p_sync;
    cudaGetSymbolAddress(&p_fps,  fpsflag);
    cudaGetSymbolAddress(&p_ball, ballflag);
    cudaGetSymbolAddress(&p_sync, d_sync);
    cudaMemsetAsync(p_fps,  0, NC*sizeof(int));
    cudaMemsetAsync(p_ball, 0, NC*sizeof(int));
    cudaMemsetAsync(p_sync, 0, 4*sizeof(int));

    cudaFuncSetAttribute(mega, cudaFuncAttributeMaxDynamicSharedMemorySize, SM_TOT);

    int mode = 0;
    int used = NC*HH;
    if (out_size >= NC*HH + NC*3)      { mode |= 1; used = NC*HH + NC*3; }
    if (out_size >= NC*HH + NC*3 + NC) { mode |= 2; used = NC*HH + NC*3 + NC; }

    mega<<<NGRID, 256, SM_TOT>>>(x, pos, W1, b1, W2, b2, out, mode);

    if (out_size > used) {
        int n = out_size - used;
        k_fill<<<(n + 255)/256, 256>>>(out, used, n);
    }
}

// round 11
// speedup vs baseline: 2.2092x; 1.7845x over previous
#include <cuda_runtime.h>
#include <cuda_bf16.h>
#include <cstdint>

#define BB      8
#define NP      4096
#define NS      1024
#define NC      (BB*NS)
#define KNBR    64
#define CIN     64
#define HH      128
#define R2f     0.04f
#define CAP     768
#define NBALL   32
#define NGRID   148
#define NGTASK  1024
#define NTTASK  4096
#define BSTR    272

// ---------------- device scratch ----------------
__device__ float g_feat[BB*NP*HH];
__device__ int   fpsflag[NC];          // idx+1 when ready (payload-in-flag)
__device__ int   ballflag[NC];         // 1 when nbr/ctr ready
__device__ int   d_nbr[NC*KNBR];       // padded to 64
__device__ float d_ctr[NC*3];
__device__ int   d_sync[4];            // 0:g_ctr 2:gemm_ctr 3:g_done

// ---------------- helpers ----------------
__device__ __forceinline__ float dist2(float ax,float ay,float az,float bx,float by,float bz){
    float dx = ax-bx, dy = ay-by, dz = az-bz;
    return __fadd_rn(__fadd_rn(__fmul_rn(dx,dx),__fmul_rn(dy,dy)),__fmul_rn(dz,dz));
}
__device__ __forceinline__ unsigned long long packf2(float lo, float hi){
    unsigned long long r; asm("mov.b64 %0, {%1, %2};" : "=l"(r) : "f"(lo), "f"(hi)); return r;
}
__device__ __forceinline__ void unpackf2(unsigned long long v, float& lo, float& hi){
    asm("mov.b64 {%0, %1}, %2;" : "=f"(lo), "=f"(hi) : "l"(v));
}
__device__ __forceinline__ unsigned long long addf2(unsigned long long a, unsigned long long b){
    unsigned long long d; asm("add.rn.f32x2 %0, %1, %2;" : "=l"(d) : "l"(a), "l"(b)); return d;
}
__device__ __forceinline__ unsigned long long mulf2(unsigned long long a, unsigned long long b){
    unsigned long long d; asm("mul.rn.f32x2 %0, %1, %2;" : "=l"(d) : "l"(a), "l"(b)); return d;
}
__device__ __forceinline__ uint32_t smem_u32(const void* p){
    uint32_t a;
    asm("{ .reg .u64 t; cvta.to.shared.u64 t, %1; cvt.u32.u64 %0, t; }" : "=r"(a) : "l"(p));
    return a;
}
__device__ __forceinline__ int ld_acq(const int* p){
    int v; asm volatile("ld.acquire.gpu.global.s32 %0, [%1];" : "=r"(v) : "l"(p) : "memory"); return v;
}
__device__ __forceinline__ void st_rel(int* p, int v){
    asm volatile("st.release.gpu.global.s32 [%0], %1;" :: "l"(p), "r"(v) : "memory");
}
__device__ __forceinline__ int ld_rlx(const int* p){
    int v; asm volatile("ld.relaxed.gpu.global.s32 %0, [%1];" : "=r"(v) : "l"(p) : "memory"); return v;
}
__device__ __forceinline__ void st_rlx(int* p, int v){
    asm volatile("st.relaxed.gpu.global.s32 [%0], %1;" :: "l"(p), "r"(v) : "memory");
}
__device__ __forceinline__ void ldsm4(uint32_t& r0,uint32_t& r1,uint32_t& r2,uint32_t& r3,uint32_t a){
    asm volatile("ldmatrix.sync.aligned.m8n8.x4.shared.b16 {%0,%1,%2,%3}, [%4];"
        : "=r"(r0),"=r"(r1),"=r"(r2),"=r"(r3) : "r"(a));
}
__device__ __forceinline__ void ldsm4t(uint32_t& r0,uint32_t& r1,uint32_t& r2,uint32_t& r3,uint32_t a){
    asm volatile("ldmatrix.sync.aligned.m8n8.x4.trans.shared.b16 {%0,%1,%2,%3}, [%4];"
        : "=r"(r0),"=r"(r1),"=r"(r2),"=r"(r3) : "r"(a));
}
__device__ __forceinline__ void mma16816(float* d, const uint32_t* a, const uint32_t* b){
    asm volatile("mma.sync.aligned.m16n8k16.row.col.f32.bf16.bf16.f32 "
        "{%0,%1,%2,%3}, {%4,%5,%6,%7}, {%8,%9}, {%0,%1,%2,%3};"
        : "+f"(d[0]),"+f"(d[1]),"+f"(d[2]),"+f"(d[3])
        : "r"(a[0]),"r"(a[1]),"r"(a[2]),"r"(a[3]), "r"(b[0]),"r"(b[1]));
}

// ---------------- smem layout (GEMM) ----------------
#define OA_HI   0
#define OA_LO   34816
#define OB_HI   69632
#define OB_LO   104448
#define OWB     139264
#define ODP     141312
#define OGJ     143360
#define OTASK   143872
#define SM_TOT  143888

// ---------------- smem layout (ball extra) ----------------
#define B_CNTR  98304                  // int[16]: per-warp {strict, tie} counters

// ---------------- smem layout (FPS) ----------------
#define F_OPX   0
#define F_OPY   16384
#define F_OPZ   32768
#define F_SPT   49152
#define F_SID   114688
#define F_CNT   131072
#define F_COFF  132100
#define F_SLOT  133128

// ===== FPS role: sorted 16-pt register chunks + bbox prune, exact =====
__device__ void fps_role(char* smem, const float* __restrict__ pos, int b)
{
    float* opx = (float*)(smem + F_OPX);
    float* opy = (float*)(smem + F_OPY);
    float* opz = (float*)(smem + F_OPZ);
    float4* spt = (float4*)(smem + F_SPT);
    int*   sid  = (int*)(smem + F_SID);
    int*   cnt  = (int*)(smem + F_CNT);
    int*   coff = (int*)(smem + F_COFF);
    unsigned long long* slots = (unsigned long long*)(smem + F_SLOT);
    int tid = threadIdx.x, lane = tid & 31, warp = tid >> 5;

    const float* pb = pos + (size_t)b*NP*3;
    for (int i = tid; i < NP; i += 256) {
        opx[i] = pb[i*3+0]; opy[i] = pb[i*3+1]; opz[i] = pb[i*3+2];
    }
    if (tid < 257) cnt[tid] = 0;
    __syncthreads();

    // counting sort by 8x8x4 cell (spatial coherence for tight per-thread bboxes)
    for (int i = tid; i < NP; i += 256) {
        int cx = min(7, (int)(opx[i]*8.0f));
        int cy = min(7, (int)(opy[i]*8.0f));
        int cz = min(3, (int)(opz[i]*4.0f));
        atomicAdd(&cnt[cx*32 + cy*4 + cz], 1);
    }
    __syncthreads();
    if (tid == 0) {
        int run = 0;
        for (int c = 0; c < 256; ++c) { int t = cnt[c]; cnt[c] = run; run += t; }
        cnt[256] = NP;
    }
    __syncthreads();
    if (tid < 256) coff[tid] = cnt[tid];
    __syncthreads();
    for (int i = tid; i < NP; i += 256) {
        int cx = min(7, (int)(opx[i]*8.0f));
        int cy = min(7, (int)(opy[i]*8.0f));
        int cz = min(3, (int)(opz[i]*4.0f));
        int o = atomicAdd(&coff[cx*32 + cy*4 + cz], 1);
        float4 v; v.x = opx[i]; v.y = opy[i]; v.z = opz[i]; v.w = 0.f;
        spt[o] = v; sid[o] = i;
    }
    if (tid == 0) st_rlx(&fpsflag[b*NS], 1);
    __syncthreads();

    // load my 16 contiguous sorted points into registers
    int base16 = tid << 4;
    float xx[16], yy[16], zz[16], md[16];
    unsigned pidr[16];
    float bx0 = 3e38f, bx1 = -3e38f, by0 = 3e38f, by1 = -3e38f, bz0 = 3e38f, bz1 = -3e38f;
    #pragma unroll
    for (int j = 0; j < 16; ++j) {
        float4 v = spt[base16 + j];
        xx[j] = v.x; yy[j] = v.y; zz[j] = v.z;
        md[j] = 1e10f;
        pidr[j] = (unsigned)(NP - 1 - sid[base16 + j]);
        bx0 = fminf(bx0, v.x); bx1 = fmaxf(bx1, v.x);
        by0 = fminf(by0, v.y); by1 = fmaxf(by1, v.y);
        bz0 = fminf(bz0, v.z); bz1 = fmaxf(bz1, v.z);
    }
    unsigned long long rx[8], ry[8], rz[8];
    #pragma unroll
    for (int j = 0; j < 8; ++j) {
        rx[j] = packf2(xx[2*j], xx[2*j+1]);
        ry[j] = packf2(yy[2*j], yy[2*j+1]);
        rz[j] = packf2(zz[2*j], zz[2*j+1]);
    }
    float smax = 1e10f;
    unsigned long long bestp = 0ull;

    int last = 0;
    for (int s = 1; s < NS; ++s) {
        float lx = opx[last], ly = opy[last], lz = opz[last];
        float ddx = fmaxf(fmaxf(bx0 - lx, lx - bx1), 0.0f);
        float ddy = fmaxf(fmaxf(by0 - ly, ly - by1), 0.0f);
        float ddz = fmaxf(fmaxf(bz0 - lz, lz - bz1), 0.0f);
        float dmin2 = ddx*ddx + ddy*ddy + ddz*ddz;
        if (!(dmin2 > smax * 1.00001f)) {
            unsigned long long nx = packf2(-lx,-lx), ny = packf2(-ly,-ly), nz = packf2(-lz,-lz);
            #pragma unroll
            for (int j = 0; j < 8; ++j) {
                unsigned long long dx = addf2(rx[j], nx);
                unsigned long long dy = addf2(ry[j], ny);
                unsigned long long dz = addf2(rz[j], nz);
                unsigned long long sD = addf2(addf2(mulf2(dx,dx), mulf2(dy,dy)), mulf2(dz,dz));
                float s0, s1; unpackf2(sD, s0, s1);
                md[2*j]   = fminf(md[2*j],   s0);
                md[2*j+1] = fminf(md[2*j+1], s1);
            }
            // packed argmax (exact global tie-break: value desc, orig idx asc)
            unsigned long long bp = 0ull;
            #pragma unroll
            for (int t = 0; t < 16; ++t) {
                unsigned long long p =
                    ((unsigned long long)__float_as_uint(md[t]) << 32) | pidr[t];
                if (p > bp) bp = p;
            }
            bestp = bp;
            smax = __uint_as_float((unsigned)(bp >> 32));
        }
        unsigned vb = (unsigned)(bestp >> 32);
        unsigned vm = __reduce_max_sync(0xffffffffu, vb);
        unsigned lo = (vb == vm) ? (unsigned)bestp : 0u;
        unsigned lm = __reduce_max_sync(0xffffffffu, lo);
        if (lane == 0)
            slots[(s & 1)*8 + warp] = ((unsigned long long)vm << 32) | lm;
        __syncthreads();
        unsigned long long w = slots[(s & 1)*8];
        #pragma unroll
        for (int k = 1; k < 8; ++k) {
            unsigned long long v = slots[(s & 1)*8 + k];
            if (v > w) w = v;
        }
        last = NP - 1 - (int)(unsigned)(w & 0xffffffffull);
        if (tid == 0) st_rlx(&fpsflag[b*NS + s], last + 1);
    }
}

// ================= ball role: hardened threshold select =================
__device__ void ball_role(char* smem, const float* __restrict__ pos,
                          float* __restrict__ out, int mode, int wkr)
{
    float* px = (float*)smem;
    float* py = px + NP;
    float* pz = py + NP;
    unsigned long long* cball = (unsigned long long*)(pz + NP);
    int* wcnt = (int*)(smem + B_CNTR);
    int tid = threadIdx.x, lane = tid & 31, wid = tid >> 5;

    int cloud = wkr & 7, lc0 = wkr >> 3;

    const float* pb = pos + (size_t)cloud*NP*3;
    for (int i = tid; i < NP; i += 256) {
        px[i] = pb[i*3+0]; py[i] = pb[i*3+1]; pz[i] = pb[i*3+2];
    }
    __syncthreads();

    for (int lc = lc0; lc < 128; lc += 4) {
        int cg = cloud*NS + lc*8 + wid;

        int v = 0;
        if (lane == 0) while ((v = ld_rlx(&fpsflag[cg])) == 0) __nanosleep(32);
        v = __shfl_sync(0xffffffffu, v, 0);
        int ci = v - 1;

        float cx = px[ci], cy = py[ci], cz = pz[ci];
        if (lane == 0) {
            d_ctr[cg*3+0] = cx; d_ctr[cg*3+1] = cy; d_ctr[cg*3+2] = cz;
            if (mode & 1) {
                out[NC*HH + cg*3+0] = cx;
                out[NC*HH + cg*3+1] = cy;
                out[NC*HH + cg*3+2] = cz;
            }
            if (mode & 2) out[NC*HH + NC*3 + cg] = (float)cloud;
        }

        unsigned long long* cb = cball + (size_t)wid * CAP;
        unsigned cnt = 0;
        for (int j = lane; j < NP; j += 32) {
            float d2 = dist2(px[j],py[j],pz[j],cx,cy,cz);
            bool in = (d2 <= R2f);
            unsigned m = __ballot_sync(0xffffffffu, in);
            if (in) {
                unsigned o = cnt + __popc(m & ((1u << lane) - 1u));
                if (o < CAP)
                    cb[o] = ((unsigned long long)__float_as_uint(d2) << 32) | (unsigned)j;
            }
            cnt += __popc(m);
        }
        if (cnt > CAP) cnt = CAP;

        int base = cg * KNBR;
        int padIdx = cloud*NP + ci;
        if (cnt <= KNBR) {
            for (int t = lane; t < KNBR; t += 32)
                d_nbr[base + t] = (t < (int)cnt)
                    ? cloud*NP + (int)(unsigned)(cb[t] & 0xffffffffull) : padIdx;
        } else if (cnt <= 256) {
            unsigned h32[8], l32[8];
            #pragma unroll
            for (int q = 0; q < 8; ++q) {
                int p = lane + q*32;
                unsigned long long vv = (p < (int)cnt) ? cb[p] : ~0ull;
                h32[q] = (unsigned)(vv >> 32);
                l32[q] = (unsigned)vv;
            }
            unsigned slo = 0u, shi = 0x3D23D70Bu;
            while (shi > slo) {
                unsigned mid = (slo + shi) >> 1;
                int c = 0;
                #pragma unroll
                for (int q = 0; q < 8; ++q) c += (h32[q] <= mid) ? 1 : 0;
                c = __reduce_add_sync(0xffffffffu, c);
                if (c >= KNBR) shi = mid; else slo = mid + 1;
            }
            unsigned T = slo;

            int* wc = wcnt + wid*2;
            if (lane == 0) { wc[0] = 0; wc[1] = 0; }
            __syncwarp();
            unsigned long long* tb = cb + 512;
            #pragma unroll
            for (int q = 0; q < 8; ++q) {
                if (h32[q] < T) {
                    int p = atomicAdd(&wc[0], 1);
                    if (p < KNBR) d_nbr[base + p] = cloud*NP + (int)l32[q];
                } else if (h32[q] == T) {
                    int p = atomicAdd(&wc[1], 1);
                    if (p < 256) tb[p] = ((unsigned long long)T << 32) | l32[q];
                }
            }
            __syncwarp();
            int ns = wc[0]; if (ns > KNBR) ns = KNBR;
            int tc = wc[1]; if (tc > 256) tc = 256;
            int r = KNBR - ns;
            if (r > tc) r = tc;
            if (r < 0) r = 0;

            for (int t = 0; t < r; ++t) {
                unsigned long long bv = ~0ull; int bp = 0;
                for (int p = lane; p < tc; p += 32) {
                    unsigned long long vv = tb[p];
                    if (vv < bv) { bv = vv; bp = p; }
                }
                #pragma unroll
                for (int off = 16; off; off >>= 1) {
                    unsigned long long ov = __shfl_xor_sync(0xffffffffu, bv, off);
                    int op = __shfl_xor_sync(0xffffffffu, bp, off);
                    if (ov < bv) { bv = ov; bp = op; }
                }
                if (lane == 0 && bv != ~0ull) {
                    d_nbr[base + ns + t] = cloud*NP + (int)(unsigned)(bv & 0xffffffffull);
                    tb[bp] = ~0ull;
                }
                __syncwarp();
            }
            for (int t = ns + r + lane; t < KNBR; t += 32)
                d_nbr[base + t] = padIdx;
        } else {
            for (int t = 0; t < KNBR; ++t) {
                unsigned long long bv = ~0ull; int bp = 0;
                for (int p = lane; p < (int)cnt; p += 32) {
                    unsigned long long vv = cb[p];
                    if (vv < bv) { bv = vv; bp = p; }
                }
                #pragma unroll
                for (int off = 16; off; off >>= 1) {
                    unsigned long long ov = __shfl_xor_sync(0xffffffffu, bv, off);
                    int op = __shfl_xor_sync(0xffffffffu, bp, off);
                    if (ov < bv) { bv = ov; bp = op; }
                }
                if (lane == 0) {
                    d_nbr[base + t] = cloud*NP + (int)(unsigned)(bv & 0xffffffffull);
                    cb[bp] = ~0ull;
                }
                __syncwarp();
            }
        }
        __threadfence();
        __syncwarp();
        if (lane == 0) st_rel(&ballflag[cg], 1);
    }
}

__device__ void g_role(char* smem, const float* __restrict__ x,
                       const float* __restrict__ W1)
{
    float* sW = (float*)smem;
    float* sx = sW + 64*HH;
    int* stask = (int*)(smem + OTASK);
    int tid = threadIdx.x;
    int ndone = 0;

    for (int i = tid; i < 64*HH; i += 256) sW[i] = W1[i];

    for (;;) {
        __syncthreads();
        if (tid == 0) *stask = atomicAdd(&d_sync[0], 1);
        __syncthreads();
        int task = *stask;
        if (task >= NGTASK) break;
        int rbase = task * 32;
        for (int i = tid; i < 32*CIN; i += 256) {
            int r = i >> 6, c = i & 63;
            sx[i] = x[(size_t)(rbase + r)*CIN + c];
        }
        __syncthreads();
        #pragma unroll
        for (int pimg = 0; pimg < 16; ++pimg) {
            int o = tid + pimg*256;
            int r = o >> 7, col = o & 127;
            float acc = 0.0f;
            const float* xr = sx + r*CIN;
            #pragma unroll 16
            for (int c = 0; c < CIN; ++c)
                acc = fmaf(xr[c], sW[c*HH + col], acc);
            g_feat[(size_t)(rbase + r)*HH + col] = acc;
        }
        ++ndone;
    }
    __threadfence();
    __syncthreads();
    if (tid == 0 && ndone) atomicAdd(&d_sync[3], ndone);
}

// ---- GEMM role: bf16-split mma.sync, 3 passes, register max epilogue ----
__device__ void gemm_role(char* smem, const float* __restrict__ pos,
                          const float* __restrict__ W1, const float* __restrict__ b1,
                          const float* __restrict__ W2, const float* __restrict__ b2,
                          float* __restrict__ out)
{
    uint32_t sbase = smem_u32(smem);
    int t = threadIdx.x, w = t >> 5, lane = t & 31;
    int* stask = (int*)(smem + OTASK);

    for (int idx = t; idx < HH*HH; idx += 256) {
        int k = idx >> 7, m = idx & 127;
        float v = W2[idx];
        __nv_bfloat16 hi = __float2bfloat16_rn(v);
        __nv_bfloat16 lo = __float2bfloat16_rn(v - __bfloat162float(hi));
        *(__nv_bfloat16*)(smem + OA_HI + m*BSTR + k*2) = hi;
        *(__nv_bfloat16*)(smem + OA_LO + m*BSTR + k*2) = lo;
    }
    if (t < HH) {
        float4 wb;
        wb.x = b1[t];
        wb.y = W1[64*HH + t]; wb.z = W1[65*HH + t]; wb.w = W1[66*HH + t];
        *(float4*)(smem + OWB + t*16) = wb;
    }
    if (t == 0) while (ld_acq(&d_sync[3]) < NGTASK) __nanosleep(128);
    __syncthreads();

    int g = lane >> 3, r = lane & 7;
    uint32_t aoff = (uint32_t)((16*w + r + (g&1)*8)*BSTR + (g>>1)*16);
    uint32_t boff = (uint32_t)((r + (g&1)*8)*BSTR + (g>>1)*16);
    int rowA = 16*w + (lane >> 2);
    float b2A = b2[rowA], b2B = b2[rowA + 8];

    for (;;) {
        __syncthreads();
        if (t == 0) *stask = atomicAdd(&d_sync[2], 1);
        __syncthreads();
        int tile = *stask;
        if (tile >= NTTASK) break;
        int cloud = tile & 7, lt = tile >> 3;
        int cg0 = cloud*NS + lt*2;

        if (t < 2) { while (ld_acq(&ballflag[cg0 + t]) == 0) __nanosleep(64); }
        __syncthreads();

        if (t < HH) {
            int cgx = cg0 + (t >> 6);
            int gj = d_nbr[cgx*KNBR + (t & 63)];
            *(int*)(smem + OGJ + t*4) = gj;
            float4 dp;
            dp.x = pos[(size_t)gj*3+0] - d_ctr[cgx*3+0];
            dp.y = pos[(size_t)gj*3+1] - d_ctr[cgx*3+1];
            dp.z = pos[(size_t)gj*3+2] - d_ctr[cgx*3+2];
            dp.w = 0.f;
            *(float4*)(smem + ODP + t*16) = dp;
        }
        __syncthreads();

        {
            int n = t & 127, kh = t >> 7;
            int gj = *(int*)(smem + OGJ + n*4);
            float4 dp = *(float4*)(smem + ODP + n*16);
            const float4* grow = (const float4*)(g_feat + (size_t)gj*HH + kh*64);
            const float4* swb = (const float4*)(smem + OWB);
            #pragma unroll 4
            for (int q = 0; q < 16; ++q) {
                float4 g4 = __ldg(grow + q);
                int k0 = kh*64 + q*4;
                float gv[4] = {g4.x, g4.y, g4.z, g4.w};
                #pragma unroll
                for (int rr = 0; rr < 4; ++rr) {
                    float4 wb = swb[k0 + rr];
                    float v = gv[rr] + wb.x;
                    v = fmaf(dp.x, wb.y, v);
                    v = fmaf(dp.y, wb.z, v);
                    v = fmaf(dp.z, wb.w, v);
                    float h = fmaxf(v, 0.0f);
                    __nv_bfloat16 hi = __float2bfloat16_rn(h);
                    __nv_bfloat16 lo = __float2bfloat16_rn(h - __bfloat162float(hi));
                    *(__nv_bfloat16*)(smem + OB_HI + (k0+rr)*BSTR + n*2) = hi;
                    *(__nv_bfloat16*)(smem + OB_LO + (k0+rr)*BSTR + n*2) = lo;
                }
            }
        }
        __syncthreads();

        float acc[16][4];
        #pragma unroll
        for (int nt = 0; nt < 16; ++nt)
            #pragma unroll
            for (int i = 0; i < 4; ++i) acc[nt][i] = 0.0f;

        #pragma unroll 1
        for (int kt = 0; kt < 8; ++kt) {
            uint32_t ahk[4], alk[4], bq[32];
            uint32_t abase = sbase + (uint32_t)(32*kt) + aoff;
            ldsm4(ahk[0],ahk[1],ahk[2],ahk[3], abase + OA_HI);
            ldsm4(alk[0],alk[1],alk[2],alk[3], abase + OA_LO);
            uint32_t bbase = sbase + (uint32_t)(16*kt)*BSTR + boff;
            #pragma unroll
            for (int tp = 0; tp < 8; ++tp)
                ldsm4t(bq[4*tp],bq[4*tp+1],bq[4*tp+2],bq[4*tp+3],
                       bbase + OB_HI + (uint32_t)(32*tp));
            #pragma unroll
            for (int nt = 0; nt < 16; ++nt) {
                mma16816(acc[nt], ahk, bq + 2*nt);
                mma16816(acc[nt], alk, bq + 2*nt);
            }
            #pragma unroll
            for (int tp = 0; tp < 8; ++tp)
                ldsm4t(bq[4*tp],bq[4*tp+1],bq[4*tp+2],bq[4*tp+3],
                       bbase + OB_LO + (uint32_t)(32*tp));
            #pragma unroll
            for (int nt = 0; nt < 16; ++nt)
                mma16816(acc[nt], ahk, bq + 2*nt);
        }

        float mA0 = -3e38f, mB0 = -3e38f, mA1 = -3e38f, mB1 = -3e38f;
        #pragma unroll
        for (int nt = 0; nt < 8; ++nt) {
            mA0 = fmaxf(mA0, fmaxf(acc[nt][0], acc[nt][1]));
            mB0 = fmaxf(mB0, fmaxf(acc[nt][2], acc[nt][3]));
            mA1 = fmaxf(mA1, fmaxf(acc[nt+8][0], acc[nt+8][1]));
            mB1 = fmaxf(mB1, fmaxf(acc[nt+8][2], acc[nt+8][3]));
        }
        #pragma unroll
        for (int off = 1; off <= 2; off <<= 1) {
            mA0 = fmaxf(mA0, __shfl_xor_sync(0xffffffffu, mA0, off));
            mB0 = fmaxf(mB0, __shfl_xor_sync(0xffffffffu, mB0, off));
            mA1 = fmaxf(mA1, __shfl_xor_sync(0xffffffffu, mA1, off));
            mB1 = fmaxf(mB1, __shfl_xor_sync(0xffffffffu, mB1, off));
        }
        if ((lane & 3) == 0) {
            out[(size_t)cg0*HH + rowA]           = fmaxf(mA0 + b2A, 0.0f);
            out[(size_t)cg0*HH + rowA + 8]       = fmaxf(mB0 + b2B, 0.0f);
            out[(size_t)(cg0+1)*HH + rowA]       = fmaxf(mA1 + b2A, 0.0f);
            out[(size_t)(cg0+1)*HH + rowA + 8]   = fmaxf(mB1 + b2B, 0.0f);
        }
    }
}

// ================= megakernel =================
__global__ __launch_bounds__(256, 1)
void mega(const float* __restrict__ x, const float* __restrict__ pos,
          const float* __restrict__ W1, const float* __restrict__ b1,
          const float* __restrict__ W2, const float* __restrict__ b2,
          float* __restrict__ out, int mode)
{
    extern __shared__ char smem[];
    int bid = blockIdx.x;

    if (bid < BB) {
        fps_role(smem, pos, bid);
    } else if (bid < BB + NBALL) {
        ball_role(smem, pos, out, mode, bid - BB);
    } else {
        g_role(smem, x, W1);
    }
    __syncthreads();
    gemm_role(smem, pos, W1, b1, W2, b2, out);
}

__global__ void k_fill(float* out, int start, int n) {
    int i = blockIdx.x * 256 + threadIdx.x;
    if (i < n) out[start + i] = 0.0f;
}

// ---------------- launch --------------------------------------------------
extern "C" void kernel_launch(void* const* d_in, const int* in_sizes, int n_in,
                              void* d_out, int out_size)
{
    const float* x   = (const float*)d_in[0];
    const float* pos = (const float*)d_in[1];
    const float* W1  = (const float*)d_in[2];
    const float* b1  = (const float*)d_in[3];
    const float* W2  = (const float*)d_in[4];
    const float* b2  = (const float*)d_in[5];
    float* out = (float*)d_out;

    void *p_fps, *p_ball, *p_sync;
    cudaGetSymbolAddress(&p_fps,  fpsflag);
    cudaGetSymbolAddress(&p_ball, ballflag);
    cudaGetSymbolAddress(&p_sync, d_sync);
    cudaMemsetAsync(p_fps,  0, NC*sizeof(int));
    cudaMemsetAsync(p_ball, 0, NC*sizeof(int));
    cudaMemsetAsync(p_sync, 0, 4*sizeof(int));

    cudaFuncSetAttribute(mega, cudaFuncAttributeMaxDynamicSharedMemorySize, SM_TOT);

    int mode = 0;
    int used = NC*HH;
    if (out_size >= NC*HH + NC*3)      { mode |= 1; used = NC*HH + NC*3; }
    if (out_size >= NC*HH + NC*3 + NC) { mode |= 2; used = NC*HH + NC*3 + NC; }

    mega<<<NGRID, 256, SM_TOT>>>(x, pos, W1, b1, W2, b2, out, mode);

    if (out_size > used) {
        int n = out_size - used;
        k_fill<<<(n + 255)/256, 256>>>(out, used, n);
    }
}